// round 16
// baseline (speedup 1.0000x reference)
#include <cuda_runtime.h>
#include <cstdint>

// ---------------- problem constants ----------------
#define NB   4
#define SEQ  4096
#define DIMM 512
#define NH   8
#define DHD  64
#define NF   256
#define CSZ  128
#define NCH  32
#define MTOK (NB*SEQ)            // 16384
#define QKVN (3*DIMM)            // 1536
#define NCHUNK (NB*NH*NCH)       // 1024

// ---------------- device scratch ----------------
__device__ float g_qkv  [MTOK * QKVN];
__device__ float g_kp   [NB*NH*SEQ*NF];        // k' packed frags per chunk
__device__ float g_ksumP[2 * NCHUNK * NF];
__device__ uint32_t g_att [MTOK * DIMM];
__device__ uint32_t g_xr  [MTOK * DIMM];
__device__ uint32_t g_wqr [QKVN * DIMM];
__device__ uint32_t g_wor [DIMM * DIMM];
__device__ uint32_t g_ppk [8 * 32 * 64];

__device__ __forceinline__ uint32_t f2tf32(float f) {
    uint32_t r;
    asm("cvt.rna.tf32.f32 %0, %1;" : "=r"(r) : "f"(f));
    return r;
}

__device__ __forceinline__ void mma_tf32(float acc[4],
                                         uint32_t a0, uint32_t a1, uint32_t a2, uint32_t a3,
                                         uint32_t b0, uint32_t b1)
{
    asm volatile(
        "mma.sync.aligned.m16n8k8.row.col.f32.tf32.tf32.f32 "
        "{%0,%1,%2,%3}, {%4,%5,%6,%7}, {%8,%9}, {%0,%1,%2,%3};"
        : "+f"(acc[0]), "+f"(acc[1]), "+f"(acc[2]), "+f"(acc[3])
        : "r"(a0), "r"(a1), "r"(a2), "r"(a3), "r"(b0), "r"(b1));
}

// =====================================================================
// Pack kernels (unchanged)
// =====================================================================
__global__ void pack_A_tf32(const float* __restrict__ src, uint32_t* __restrict__ dst, int n4)
{
    int gid = blockIdx.x * blockDim.x + threadIdx.x;
    if (gid >= n4) return;
    const int lane = gid & 31, sub = (gid >> 5) & 7, kg = (gid >> 8) & 1;
    const int kt = (gid >> 9) & 31, tile = gid >> 14;
    const int qr = lane >> 2, qc = lane & 3;
    const int row = tile*128 + sub*16 + qr;
    const int col = kt*16 + kg*8 + qc;
    const float* s0 = src + (size_t)row * 512 + col;
    uint4 u;
    u.x = f2tf32(s0[0]);
    u.y = f2tf32(s0[8*512]);
    u.z = f2tf32(s0[4]);
    u.w = f2tf32(s0[8*512 + 4]);
    *(uint4*)(dst + (size_t)gid * 4) = u;
}

__device__ __forceinline__ void packB_one(const float* __restrict__ src,
                                          uint32_t* __restrict__ dst, int gid)
{
    const int lane = gid & 31, nsub = (gid >> 5) & 15, kg = (gid >> 9) & 1;
    const int kt = (gid >> 10) & 31, tile = gid >> 15;
    const int qr = lane >> 2, qc = lane & 3;
    const int row = tile*128 + nsub*8 + qr;
    const int col = kt*16 + kg*8 + qc;
    const float* s0 = src + (size_t)row * 512 + col;
    uint2 u;
    u.x = f2tf32(s0[0]);
    u.y = f2tf32(s0[4]);
    *(uint2*)(dst + (size_t)gid * 2) = u;
}

#define NB1 (QKVN*DIMM/2)        // 393216
#define NB2 (DIMM*DIMM/2)        // 131072
__global__ void pack_rest(const float* __restrict__ wqkv, const float* __restrict__ wout,
                          const float* __restrict__ proj,
                          uint32_t* __restrict__ wqr, uint32_t* __restrict__ wor,
                          uint32_t* __restrict__ ppk)
{
    int gid = blockIdx.x * blockDim.x + threadIdx.x;
    if (gid < NB1) {
        packB_one(wqkv, wqr, gid);
    } else if (gid < NB1 + NB2) {
        packB_one(wout, wor, gid - NB1);
    } else if (gid < NB1 + NB2 + 8192) {
        const int g = gid - NB1 - NB2;
        const int ln = g & 31, nsub = (g >> 5) & 31, ks = g >> 10;
        const int qr = ln >> 2, qc = ln & 3;
        const int f = nsub*8 + qr;
        const int d = ks*8 + qc;
        uint2 u;
        u.x = f2tf32(proj[f*DHD + d]);
        u.y = f2tf32(proj[f*DHD + d + 4]);
        *(uint2*)(ppk + ks*2048 + nsub*64 + ln*2) = u;
    }
}

// =====================================================================
// TF32 GEMM NT (unchanged R13/R15): BK=32 stages, 3-stage pipeline.
// =====================================================================
#define TG_SMEM_BYTES (3 * 8192 * 4)     // 98304

template<bool BIAS>
__global__ __launch_bounds__(256, 2)
void tgemm_nt(const uint32_t* __restrict__ Apk, const uint32_t* __restrict__ Bpk,
              const float* __restrict__ bias, float* __restrict__ C,
              int M, int N, int K)
{
    extern __shared__ uint32_t smg[];
    const uint32_t smb = (uint32_t)__cvta_generic_to_shared(smg);

    const int tid  = threadIdx.x;
    const int lane = tid & 31;
    const int warp = tid >> 5;
    const int mg   = warp >> 1;
    const int ng   = warp & 1;
    const int qr   = lane >> 2;
    const int qc   = lane & 3;

    const int KT  = K >> 4;
    const int KT2 = K >> 5;
    const size_t aBase = (size_t)blockIdx.y * KT * 2048;
    const size_t bBase = (size_t)blockIdx.x * KT * 2048;
    const int bm = blockIdx.y * 128;
    const int bn = blockIdx.x * 128;

    auto issue = [&](int ktb, int s) {
        const uint32_t sb = smb + s * 8192 * 4;
        const uint32_t* gA = Apk + aBase + (size_t)ktb * 4096;
        const uint32_t* gB = Bpk + bBase + (size_t)ktb * 4096;
#pragma unroll
        for (int i = 0; i < 4; ++i) {
            const int j = tid + i * 256;
            asm volatile("cp.async.cg.shared.global [%0], [%1], 16;"
                         :: "r"(sb + j * 16), "l"(gA + j * 4) : "memory");
            asm volatile("cp.async.cg.shared.global [%0], [%1], 16;"
                         :: "r"(sb + 16384 + j * 16), "l"(gB + j * 4) : "memory");
        }
    };

    float acc[2][8][4];
#pragma unroll
    for (int i = 0; i < 2; i++)
#pragma unroll
        for (int nt = 0; nt < 8; nt++)
#pragma unroll
            for (int c = 0; c < 4; c++) acc[i][nt][c] = 0.f;

    issue(0, 0);
    asm volatile("cp.async.commit_group;" ::: "memory");
    issue(1, 1);
    asm volatile("cp.async.commit_group;" ::: "memory");

    int stg = 0;
    for (int ktb = 0; ktb < KT2; ++ktb) {
        asm volatile("cp.async.wait_group 1;" ::: "memory");
        __syncthreads();
        const uint32_t* st = smg + stg * 8192;
#pragma unroll
        for (int sk = 0; sk < 4; ++sk) {
            const uint32_t* ab = st + sk * 1024;
            const uint32_t* bb = st + 4096 + sk * 1024;
            uint4 a[2];
#pragma unroll
            for (int i = 0; i < 2; i++)
                a[i] = *(const uint4*)&ab[(mg*2 + i) * 128 + lane*4];
            uint2 bf[8];
#pragma unroll
            for (int nt = 0; nt < 8; nt++)
                bf[nt] = *(const uint2*)&bb[(ng*8 + nt) * 64 + lane*2];
#pragma unroll
            for (int i = 0; i < 2; i++)
#pragma unroll
                for (int nt = 0; nt < 8; nt++)
                    mma_tf32(acc[i][nt], a[i].x, a[i].y, a[i].z, a[i].w,
                             bf[nt].x, bf[nt].y);
        }
        if (ktb + 2 < KT2) {
            const int ns = (stg + 2 >= 3) ? stg - 1 : stg + 2;
            issue(ktb + 2, ns);
        }
        asm volatile("cp.async.commit_group;" ::: "memory");
        stg = (stg + 1 == 3) ? 0 : stg + 1;
    }

#pragma unroll
    for (int i = 0; i < 2; i++) {
        const int r0 = bm + (mg*2 + i) * 16 + qr;
#pragma unroll
        for (int nt = 0; nt < 8; nt++) {
            const int c0 = bn + (ng*8 + nt) * 8 + 2*qc;
            float v0 = acc[i][nt][0], v1 = acc[i][nt][1];
            float v2 = acc[i][nt][2], v3 = acc[i][nt][3];
            if (BIAS) {
                const float b0 = __ldg(bias + c0), b1 = __ldg(bias + c0 + 1);
                v0 += b0; v1 += b1; v2 += b0; v3 += b1;
            }
            *(float2*)(C + (size_t)r0       * N + c0) = make_float2(v0, v1);
            *(float2*)(C + (size_t)(r0 + 8) * N + c0) = make_float2(v2, v3);
        }
    }
}

// =====================================================================
// Feature kernel — K ONLY now (q' computed inside ctx_out_fused).
// Half-chunk blocks, 2 CTAs/SM. grid = (NCHUNK, 2): y = half.
// =====================================================================
#define FAPK_HSTRIDE 516
#define FRMAX_BASE  16896
#define FEAT_SMEM_BYTES (17152 * 4)

__global__ __launch_bounds__(256, 2)
void feature_k(const uint32_t* __restrict__ Ppk)
{
    extern __shared__ uint32_t smu[];
    uint32_t* APK = smu;
    float*    sm_e = (float*)smu;
    float*    RMAX = (float*)(smu + FRMAX_BASE);

    const int cid  = blockIdx.x;
    const int half = blockIdx.y;
    const int b  = cid >> 8;
    const int h  = (cid >> 5) & 7;
    const int cc = cid & 31;
    const size_t row0h  = (size_t)b * SEQ + (size_t)cc * CSZ + half * 64;
    const int   colbase = DIMM + h * DHD;      // k part
    const int tid  = threadIdx.x;
    const int lane = tid & 31;
    const int warp = tid >> 5;
    const int wgm  = warp >> 2;
    const int fg   = warp & 3;
    const int qr   = lane >> 2;
    const int qc   = lane & 3;

#pragma unroll
    for (int it = 0; it < 4; ++it) {
        const int idx4 = it * 256 + tid;
        const int s  = idx4 >> 4;
        const int d4 = (idx4 & 15) * 4;
        float4 v = *(const float4*)(g_qkv + (row0h + s) * QKVN + colbase + d4);
        const int ks   = d4 >> 3;
        const int hi   = (d4 >> 2) & 1;
        const int sub  = s >> 4;
        const int qrS  = s & 7;
        const int halfS= (s >> 3) & 1;
        const int word = hi * 2 + halfS;
        uint32_t* base = APK + ks * FAPK_HSTRIDE + sub * 128 + (qrS << 4);
        base[0*4 + word] = f2tf32(v.x);
        base[1*4 + word] = f2tf32(v.y);
        base[2*4 + word] = f2tf32(v.z);
        base[3*4 + word] = f2tf32(v.w);
    }
    __syncthreads();

    float acc[2][8][4];
#pragma unroll
    for (int mt = 0; mt < 2; mt++)
#pragma unroll
        for (int nt = 0; nt < 8; nt++)
#pragma unroll
            for (int c = 0; c < 4; c++) acc[mt][nt][c] = 0.f;

    const int rl4 = lane * 4;
#pragma unroll
    for (int ks = 0; ks < 8; ++ks) {
        const uint32_t* abase = APK + ks * FAPK_HSTRIDE;
        const uint32_t* pbase = Ppk + ks * 2048;
        uint4 a0 = *(const uint4*)&abase[(wgm*2 + 0) * 128 + rl4];
        uint4 a1 = *(const uint4*)&abase[(wgm*2 + 1) * 128 + rl4];
#pragma unroll
        for (int nt = 0; nt < 8; nt++) {
            uint2 bb = __ldg((const uint2*)&pbase[(fg*8 + nt) * 64 + lane*2]);
            mma_tf32(acc[0][nt], a0.x, a0.y, a0.z, a0.w, bb.x, bb.y);
            mma_tf32(acc[1][nt], a1.x, a1.y, a1.z, a1.w, bb.x, bb.y);
        }
    }

    float mloc[2][2];
#pragma unroll
    for (int mt = 0; mt < 2; mt++)
#pragma unroll
        for (int hh = 0; hh < 2; hh++) {
            float m = -1e30f;
#pragma unroll
            for (int nt = 0; nt < 8; nt++) {
                m = fmaxf(m, acc[mt][nt][hh*2+0]);
                m = fmaxf(m, acc[mt][nt][hh*2+1]);
            }
            m = fmaxf(m, __shfl_xor_sync(0xffffffffu, m, 1));
            m = fmaxf(m, __shfl_xor_sync(0xffffffffu, m, 2));
            mloc[mt][hh] = m;
        }
    if (qc == 0) {
#pragma unroll
        for (int mt = 0; mt < 2; mt++)
#pragma unroll
            for (int hh = 0; hh < 2; hh++)
                RMAX[fg*64 + wgm*32 + mt*16 + hh*8 + qr] = mloc[mt][hh];
    }
    __syncthreads();

    float rm[2][2];
#pragma unroll
    for (int mt = 0; mt < 2; mt++)
#pragma unroll
        for (int hh = 0; hh < 2; hh++) {
            const int row = wgm*32 + mt*16 + hh*8 + qr;
            float m = fmaxf(RMAX[row], RMAX[64 + row]);
            m = fmaxf(m, RMAX[128 + row]);
            rm[mt][hh] = fmaxf(m, RMAX[192 + row]);
        }

#pragma unroll
    for (int mt = 0; mt < 2; mt++)
#pragma unroll
        for (int hh = 0; hh < 2; hh++) {
            const int row = wgm*32 + mt*16 + hh*8 + qr;
#pragma unroll
            for (int nt = 0; nt < 8; nt++) {
                const int f = fg*64 + nt*8 + 2*qc;
                float e0 = __expf(acc[mt][nt][hh*2+0] - rm[mt][hh]);
                float e1 = __expf(acc[mt][nt][hh*2+1] - rm[mt][hh]);
                sm_e[row*264 + f]     = __uint_as_float(f2tf32(e0));
                sm_e[row*264 + f + 1] = __uint_as_float(f2tf32(e1));
            }
        }
    __syncthreads();

    // k' half -> packed A-frags [ks16][sub16][lane][w4], ks in [8h, 8h+8)
    uint32_t* outp = (uint32_t*)g_kp + (size_t)cid * 32768;
#pragma unroll
    for (int it = 0; it < 16; ++it) {
        const int gid = it * 256 + tid;
        const int ln  = gid & 31;
        const int sub = (gid >> 5) & 15;
        const int ksl = gid >> 9;
        const int ks  = half*8 + ksl;
        const int qc2 = ln & 3, qr2 = ln >> 2;
        const int s0l = ksl*8 + qc2;
        const int f0  = sub*16 + qr2;
        uint4 u;
        u.x = __float_as_uint(sm_e[s0l*264 + f0]);
        u.y = __float_as_uint(sm_e[s0l*264 + f0 + 8]);
        u.z = __float_as_uint(sm_e[(s0l+4)*264 + f0]);
        u.w = __float_as_uint(sm_e[(s0l+4)*264 + f0 + 8]);
        *(uint4*)(outp + (size_t)(ks*2048 + sub*128 + ln*4)) = u;
    }
    float s = 0.f;
#pragma unroll 8
    for (int r = 0; r < 64; ++r) s += sm_e[r*264 + tid];
    g_ksumP[((size_t)half * NCHUNK + cid) * NF + tid] = s;
}

// =====================================================================
// Fused ctx + out kernel with in-kernel q-feature (q' never hits gmem).
// 1 CTA/SM (accq = 128 regs). Warp w owns s-rows [16w, 16w+16).
// smem (u32): region0 @0: 16384 (vpl -> CBp -> ATs)
//             VBp @16384: 8192 | APK @24576: 8224 | SKf @32800: 256
// total 33056 u32 = 132224 B
// =====================================================================
#define QAPK_STRIDE 1028
#define CO_SMEM_BYTES (33056 * 4)

__global__ __launch_bounds__(256, 1)
void ctx_out_fused(const uint32_t* __restrict__ Ppk)
{
    extern __shared__ uint32_t smu[];
    float*    vpl = (float*)smu;
    uint32_t* CBp = smu;
    uint32_t* ATs = smu;
    uint32_t* VBp = smu + 16384;
    uint32_t* APK = smu + 24576;
    float*    SKf = (float*)(smu + 32800);

    const int cid = blockIdx.x;
    const int b  = cid >> 8;
    const int h  = (cid >> 5) & 7;
    const int cc = cid & 31;
    const size_t row0 = (size_t)b * SEQ + (size_t)cc * CSZ;
    const int vcol = 2 * DIMM + h * DHD;
    const int qcol = h * DHD;
    const int tid  = threadIdx.x;
    const int lane = tid & 31;
    const int warp = tid >> 5;
    const int qr   = lane >> 2;
    const int qc   = lane & 3;

    const uint32_t* kbase = (const uint32_t*)g_kp + (size_t)cid * 32768;

    // ---- 1: load v -> vpl ; SKf (fp32 sums) ----
#pragma unroll
    for (int it = 0; it < 8; ++it) {
        const int idx4 = it * 256 + tid;
        const int s  = idx4 >> 4;
        const int d4 = (idx4 & 15) * 4;
        *(float4*)(vpl + s*72 + d4) =
            *(const float4*)(g_qkv + (row0 + s) * QKVN + vcol + d4);
    }
    if (tid < NF)
        SKf[tid] = g_ksumP[(size_t)cid * NF + tid] +
                   g_ksumP[((size_t)NCHUNK + cid) * NF + tid];
    __syncthreads();

    // ---- 2: pack v into VBp ----
#pragma unroll
    for (int it = 0; it < 16; ++it) {
        const int wid2 = it * 256 + tid;
        const int ln   = wid2 & 31;
        const int nsub = (wid2 >> 5) & 7;
        const int ks   = wid2 >> 8;
        const int qc2 = ln & 3, qr2 = ln >> 2;
        const int s0 = ks*8 + qc2, d0 = nsub*8 + qr2;
        uint2 u;
        u.x = f2tf32(vpl[s0*72 + d0]);
        u.y = f2tf32(vpl[(s0+4)*72 + d0]);
        *(uint2*)(VBp + wid2*2) = u;
    }
    __syncthreads();

    // ---- 3: P1 ctx (k' A-frags from gmem + VBp) ----
    float acc1[2][8][4];
#pragma unroll
    for (int mt = 0; mt < 2; mt++)
#pragma unroll
        for (int nt = 0; nt < 8; nt++)
#pragma unroll
            for (int c = 0; c < 4; c++) acc1[mt][nt][c] = 0.f;

#pragma unroll 8
    for (int ks = 0; ks < 16; ++ks) {
        uint4 a0 = *(const uint4*)(kbase + ks*2048 + (warp*2 + 0)*128 + lane*4);
        uint4 a1 = *(const uint4*)(kbase + ks*2048 + (warp*2 + 1)*128 + lane*4);
#pragma unroll
        for (int nt = 0; nt < 8; nt++) {
            uint2 bb = *(const uint2*)(VBp + ks*512 + nt*64 + lane*2);
            mma_tf32(acc1[0][nt], a0.x, a0.y, a0.z, a0.w, bb.x, bb.y);
            mma_tf32(acc1[1][nt], a1.x, a1.y, a1.z, a1.w, bb.x, bb.y);
        }
    }
    __syncthreads();   // vpl reads done; CBp alias-write next

    // ---- 4: scatter ctx -> CBp ; load q-part -> APK ----
#pragma unroll
    for (int mt = 0; mt < 2; mt++)
#pragma unroll
        for (int nt = 0; nt < 8; nt++)
#pragma unroll
            for (int c = 0; c < 4; c++) {
                const int f = warp*32 + mt*16 + qr + ((c & 2) << 2);
                const int d = nt*8 + 2*qc + (c & 1);
                CBp[(f>>3)*512 + (d>>3)*64 + ((d&7)*4 + (f&3))*2 + ((f>>2)&1)]
                    = f2tf32(acc1[mt][nt][c]);
            }
#pragma unroll
    for (int it = 0; it < 8; ++it) {
        const int idx4 = it * 256 + tid;
        const int s  = idx4 >> 4;                 // 0..127
        const int d4 = (idx4 & 15) * 4;
        float4 v = *(const float4*)(g_qkv + (row0 + s) * QKVN + qcol + d4);
        const int ks   = d4 >> 3;
        const int hi   = (d4 >> 2) & 1;
        const int sub  = s >> 4;
        const int qrS  = s & 7;
        const int halfS= (s >> 3) & 1;
        const int word = hi * 2 + halfS;
        uint32_t* base = APK + ks * QAPK_STRIDE + sub * 128 + (qrS << 4);
        base[0*4 + word] = f2tf32(v.x * 0.125f);
        base[1*4 + word] = f2tf32(v.y * 0.125f);
        base[2*4 + word] = f2tf32(v.z * 0.125f);
        base[3*4 + word] = f2tf32(v.w * 0.125f);
    }
    __syncthreads();

    // ---- 5: q-feature, warp w -> rows [16w,16w+16), all 256 f in regs ----
    float accq[32][4];
#pragma unroll
    for (int nt = 0; nt < 32; nt++)
#pragma unroll
        for (int c = 0; c < 4; c++) accq[nt][c] = 0.f;

#pragma unroll
    for (int ks = 0; ks < 8; ++ks) {
        uint4 a = *(const uint4*)&APK[ks * QAPK_STRIDE + warp*128 + lane*4];
        const uint32_t* pbase = Ppk + ks * 2048;
#pragma unroll
        for (int nt = 0; nt < 32; nt++) {
            uint2 bb = __ldg((const uint2*)&pbase[nt*64 + lane*2]);
            mma_tf32(accq[nt], a.x, a.y, a.z, a.w, bb.x, bb.y);
        }
    }

    // in-warp rowmax (rows qr and qr+8 of this warp's 16)
    float m0 = -1e30f, m1 = -1e30f;
#pragma unroll
    for (int nt = 0; nt < 32; nt++) {
        m0 = fmaxf(m0, fmaxf(accq[nt][0], accq[nt][1]));
        m1 = fmaxf(m1, fmaxf(accq[nt][2], accq[nt][3]));
    }
    m0 = fmaxf(m0, __shfl_xor_sync(0xffffffffu, m0, 1));
    m0 = fmaxf(m0, __shfl_xor_sync(0xffffffffu, m0, 2));
    m1 = fmaxf(m1, __shfl_xor_sync(0xffffffffu, m1, 1));
    m1 = fmaxf(m1, __shfl_xor_sync(0xffffffffu, m1, 2));

    // exp + tf32-round (in place) ; D partials (fp32)
    float d0 = 0.f, d1 = 0.f;
#pragma unroll
    for (int nt = 0; nt < 32; nt++) {
        const float k0 = SKf[nt*8 + 2*qc];
        const float k1 = SKf[nt*8 + 2*qc + 1];
        float e0 = __uint_as_float(f2tf32(__expf(accq[nt][0] - m0)));
        float e1 = __uint_as_float(f2tf32(__expf(accq[nt][1] - m0)));
        float e2 = __uint_as_float(f2tf32(__expf(accq[nt][2] - m1)));
        float e3 = __uint_as_float(f2tf32(__expf(accq[nt][3] - m1)));
        accq[nt][0] = e0; accq[nt][1] = e1; accq[nt][2] = e2; accq[nt][3] = e3;
        d0 = fmaf(e0, k0, fmaf(e1, k1, d0));
        d1 = fmaf(e2, k0, fmaf(e3, k1, d1));
    }
    d0 += __shfl_xor_sync(0xffffffffu, d0, 1);
    d0 += __shfl_xor_sync(0xffffffffu, d0, 2);
    d1 += __shfl_xor_sync(0xffffffffu, d1, 1);
    d1 += __shfl_xor_sync(0xffffffffu, d1, 2);

    // transform C-frags -> A-frags (in place, per ks)
    {
        const int s1 = (lane & 28) | (qc >> 1);
        const int s2 = s1 + 2;
        const bool odd = (qc & 1) != 0;
#pragma unroll
        for (int ks = 0; ks < 32; ++ks) {
            float t0 = __shfl_sync(0xffffffffu, accq[ks][0], s1);
            float t1 = __shfl_sync(0xffffffffu, accq[ks][1], s1);
            float t2 = __shfl_sync(0xffffffffu, accq[ks][2], s1);
            float t3 = __shfl_sync(0xffffffffu, accq[ks][3], s1);
            float u0 = __shfl_sync(0xffffffffu, accq[ks][0], s2);
            float u1 = __shfl_sync(0xffffffffu, accq[ks][1], s2);
            float u2 = __shfl_sync(0xffffffffu, accq[ks][2], s2);
            float u3 = __shfl_sync(0xffffffffu, accq[ks][3], s2);
            accq[ks][0] = odd ? t1 : t0;
            accq[ks][1] = odd ? t3 : t2;
            accq[ks][2] = odd ? u1 : u0;
            accq[ks][3] = odd ? u3 : u2;
        }
    }

    // ---- 6: P2 out = q' @ ctx (A-frags in regs, B from CBp) ----
    float acc2[8][4];
#pragma unroll
    for (int nt = 0; nt < 8; nt++)
#pragma unroll
        for (int c = 0; c < 4; c++) acc2[nt][c] = 0.f;

#pragma unroll 4
    for (int ks = 0; ks < 32; ++ks) {
        const uint32_t a0 = __float_as_uint(accq[ks][0]);
        const uint32_t a1 = __float_as_uint(accq[ks][1]);
        const uint32_t a2 = __float_as_uint(accq[ks][2]);
        const uint32_t a3 = __float_as_uint(accq[ks][3]);
#pragma unroll
        for (int nt = 0; nt < 8; nt++) {
            uint2 bb = *(const uint2*)(CBp + ks*512 + nt*64 + lane*2);
            mma_tf32(acc2[nt], a0, a1, a2, a3, bb.x, bb.y);
        }
    }
    __syncthreads();    // CBp reads done; ATs alias-write next

    // ---- 7: scatter packed att + store ----
    {
        const float dinv0 = 1.0f / (d0 + 1e-4f);
        const float dinv1 = 1.0f / (d1 + 1e-4f);
#pragma unroll
        for (int nt = 0; nt < 8; nt++) {
#pragma unroll
            for (int c = 0; c < 4; c++) {
                const int r   = warp*16 + qr + (c & 2) * 4;
                const int col = nt*8 + 2*qc + (c & 1);
                const float dinv = (c & 2) ? dinv1 : dinv0;
                const int idx = (col>>4)*2048 + ((col>>3)&1)*1024 + (r>>4)*128
                              + ((r&7)*4 + (col&3))*4 + ((col>>2)&1)*2 + ((r>>3)&1);
                ATs[idx] = f2tf32(acc2[nt][c] * dinv);
            }
        }
    }
    __syncthreads();

    {
        const int tile = b*32 + cc;
        uint4* gdst = (uint4*)(g_att + (size_t)tile * 65536 + (size_t)h * 8192);
        const uint4* ssrc = (const uint4*)ATs;
#pragma unroll
        for (int i = 0; i < 8; ++i)
            gdst[i*256 + tid] = ssrc[i*256 + tid];
    }
}

// =====================================================================
// launch
// =====================================================================
extern "C" void kernel_launch(void* const* d_in, const int* in_sizes, int n_in,
                              void* d_out, int out_size)
{
    const float *x = nullptr, *wqkv = nullptr, *wout = nullptr,
                *bout = nullptr, *proj = nullptr;
    for (int i = 0; i < n_in; i++) {
        switch (in_sizes[i]) {
            case MTOK * DIMM:  x    = (const float*)d_in[i]; break;
            case QKVN * DIMM:  wqkv = (const float*)d_in[i]; break;
            case DIMM * DIMM:  wout = (const float*)d_in[i]; break;
            case DIMM:         bout = (const float*)d_in[i]; break;
            case NF * DHD:     proj = (const float*)d_in[i]; break;
        }
    }

    cudaFuncSetAttribute(feature_k,  cudaFuncAttributeMaxDynamicSharedMemorySize, FEAT_SMEM_BYTES);
    cudaFuncSetAttribute(ctx_out_fused, cudaFuncAttributeMaxDynamicSharedMemorySize, CO_SMEM_BYTES);
    cudaFuncSetAttribute(tgemm_nt<false>, cudaFuncAttributeMaxDynamicSharedMemorySize, TG_SMEM_BYTES);
    cudaFuncSetAttribute(tgemm_nt<true>,  cudaFuncAttributeMaxDynamicSharedMemorySize, TG_SMEM_BYTES);

    float *qkvp = nullptr;
    uint32_t *attp = nullptr, *xr = nullptr, *wqr = nullptr, *wor = nullptr, *ppk = nullptr;
    cudaGetSymbolAddress((void**)&qkvp, g_qkv);
    cudaGetSymbolAddress((void**)&attp, g_att);
    cudaGetSymbolAddress((void**)&xr,   g_xr);
    cudaGetSymbolAddress((void**)&wqr,  g_wqr);
    cudaGetSymbolAddress((void**)&wor,  g_wor);
    cudaGetSymbolAddress((void**)&ppk,  g_ppk);

    // 0) pack operands into tf32 fragment layouts
    pack_A_tf32<<<(MTOK*DIMM/4 + 255)/256, 256>>>(x, xr, MTOK*DIMM/4);
    pack_rest<<<(NB1 + NB2 + 8192 + 255)/256, 256>>>(wqkv, wout, proj, wqr, wor, ppk);

    // 1) qkv = x @ w_qkv^T
    tgemm_nt<false><<<dim3(QKVN/128, MTOK/128), 256, TG_SMEM_BYTES>>>(
        xr, wqr, nullptr, qkvp, MTOK, QKVN, DIMM);
    // 2) k' feature maps only (+ksum partials)
    feature_k<<<dim3(NCHUNK, 2), 256, FEAT_SMEM_BYTES>>>(ppk);
    // 3+4) fused ctx + q-feature + out -> packed att
    ctx_out_fused<<<NCHUNK, 256, CO_SMEM_BYTES>>>(ppk);
    // 5) final = att @ w_out^T + b_out
    tgemm_nt<true><<<dim3(DIMM/128, MTOK/128), 256, TG_SMEM_BYTES>>>(
        attp, wor, bout, (float*)d_out, MTOK, DIMM, DIMM);
}

// round 17
// speedup vs baseline: 1.3771x; 1.3771x over previous
#include <cuda_runtime.h>
#include <cstdint>

// ---------------- problem constants ----------------
#define NB   4
#define SEQ  4096
#define DIMM 512
#define NH   8
#define DHD  64
#define NF   256
#define CSZ  128
#define NCH  32
#define MTOK (NB*SEQ)            // 16384
#define QKVN (3*DIMM)            // 1536
#define NCHUNK (NB*NH*NCH)       // 1024

// ---------------- device scratch ----------------
__device__ float g_qkv  [MTOK * QKVN];
__device__ float g_qp   [NB*NH*SEQ*NF];
__device__ float g_kp   [NB*NH*SEQ*NF];
__device__ float g_ksumP[2 * NCHUNK * NF];
__device__ uint32_t g_att [MTOK * DIMM];
__device__ uint32_t g_xr  [MTOK * DIMM];
__device__ uint32_t g_wqr [QKVN * DIMM];
__device__ uint32_t g_wor [DIMM * DIMM];
__device__ uint32_t g_ppk [8 * 32 * 64];

__device__ __forceinline__ uint32_t f2tf32(float f) {
    uint32_t r;
    asm("cvt.rna.tf32.f32 %0, %1;" : "=r"(r) : "f"(f));
    return r;
}

__device__ __forceinline__ void mma_tf32(float acc[4],
                                         uint32_t a0, uint32_t a1, uint32_t a2, uint32_t a3,
                                         uint32_t b0, uint32_t b1)
{
    asm volatile(
        "mma.sync.aligned.m16n8k8.row.col.f32.tf32.tf32.f32 "
        "{%0,%1,%2,%3}, {%4,%5,%6,%7}, {%8,%9}, {%0,%1,%2,%3};"
        : "+f"(acc[0]), "+f"(acc[1]), "+f"(acc[2]), "+f"(acc[3])
        : "r"(a0), "r"(a1), "r"(a2), "r"(a3), "r"(b0), "r"(b1));
}

// =====================================================================
// Pack kernels
// =====================================================================
__global__ void pack_A_tf32(const float* __restrict__ src, uint32_t* __restrict__ dst, int n4)
{
    int gid = blockIdx.x * blockDim.x + threadIdx.x;
    if (gid >= n4) return;
    const int lane = gid & 31, sub = (gid >> 5) & 7, kg = (gid >> 8) & 1;
    const int kt = (gid >> 9) & 31, tile = gid >> 14;
    const int qr = lane >> 2, qc = lane & 3;
    const int row = tile*128 + sub*16 + qr;
    const int col = kt*16 + kg*8 + qc;
    const float* s0 = src + (size_t)row * 512 + col;
    uint4 u;
    u.x = f2tf32(s0[0]);
    u.y = f2tf32(s0[8*512]);
    u.z = f2tf32(s0[4]);
    u.w = f2tf32(s0[8*512 + 4]);
    *(uint4*)(dst + (size_t)gid * 4) = u;
}

__device__ __forceinline__ void packB_one(const float* __restrict__ src,
                                          uint32_t* __restrict__ dst, int gid)
{
    const int lane = gid & 31, nsub = (gid >> 5) & 15, kg = (gid >> 9) & 1;
    const int kt = (gid >> 10) & 31, tile = gid >> 15;
    const int qr = lane >> 2, qc = lane & 3;
    const int row = tile*128 + nsub*8 + qr;
    const int col = kt*16 + kg*8 + qc;
    const float* s0 = src + (size_t)row * 512 + col;
    uint2 u;
    u.x = f2tf32(s0[0]);
    u.y = f2tf32(s0[4]);
    *(uint2*)(dst + (size_t)gid * 2) = u;
}

#define NB1 (QKVN*DIMM/2)        // 393216
#define NB2 (DIMM*DIMM/2)        // 131072
__global__ void pack_rest(const float* __restrict__ wqkv, const float* __restrict__ wout,
                          const float* __restrict__ proj,
                          uint32_t* __restrict__ wqr, uint32_t* __restrict__ wor,
                          uint32_t* __restrict__ ppk)
{
    int gid = blockIdx.x * blockDim.x + threadIdx.x;
    if (gid < NB1) {
        packB_one(wqkv, wqr, gid);
    } else if (gid < NB1 + NB2) {
        packB_one(wout, wor, gid - NB1);
    } else if (gid < NB1 + NB2 + 8192) {
        const int g = gid - NB1 - NB2;
        const int ln = g & 31, nsub = (g >> 5) & 31, ks = g >> 10;
        const int qr = ln >> 2, qc = ln & 3;
        const int f = nsub*8 + qr;
        const int d = ks*8 + qc;
        uint2 u;
        u.x = f2tf32(proj[f*DHD + d]);
        u.y = f2tf32(proj[f*DHD + d + 4]);
        *(uint2*)(ppk + ks*2048 + nsub*64 + ln*2) = u;
    }
}

// =====================================================================
// TF32 GEMM NT, BK=32 stages, 3-stage cp.async pipeline, 128x128 tile,
// 2 CTAs/SM.
// =====================================================================
#define TG_SMEM_BYTES (3 * 8192 * 4)     // 98304

template<bool BIAS>
__global__ __launch_bounds__(256, 2)
void tgemm_nt(const uint32_t* __restrict__ Apk, const uint32_t* __restrict__ Bpk,
              const float* __restrict__ bias, float* __restrict__ C,
              int M, int N, int K)
{
    extern __shared__ uint32_t smg[];
    const uint32_t smb = (uint32_t)__cvta_generic_to_shared(smg);

    const int tid  = threadIdx.x;
    const int lane = tid & 31;
    const int warp = tid >> 5;
    const int mg   = warp >> 1;
    const int ng   = warp & 1;
    const int qr   = lane >> 2;
    const int qc   = lane & 3;

    const int KT  = K >> 4;
    const int KT2 = K >> 5;
    const size_t aBase = (size_t)blockIdx.y * KT * 2048;
    const size_t bBase = (size_t)blockIdx.x * KT * 2048;
    const int bm = blockIdx.y * 128;
    const int bn = blockIdx.x * 128;

    auto issue = [&](int ktb, int s) {
        const uint32_t sb = smb + s * 8192 * 4;
        const uint32_t* gA = Apk + aBase + (size_t)ktb * 4096;
        const uint32_t* gB = Bpk + bBase + (size_t)ktb * 4096;
#pragma unroll
        for (int i = 0; i < 4; ++i) {
            const int j = tid + i * 256;
            asm volatile("cp.async.cg.shared.global [%0], [%1], 16;"
                         :: "r"(sb + j * 16), "l"(gA + j * 4) : "memory");
            asm volatile("cp.async.cg.shared.global [%0], [%1], 16;"
                         :: "r"(sb + 16384 + j * 16), "l"(gB + j * 4) : "memory");
        }
    };

    float acc[2][8][4];
#pragma unroll
    for (int i = 0; i < 2; i++)
#pragma unroll
        for (int nt = 0; nt < 8; nt++)
#pragma unroll
            for (int c = 0; c < 4; c++) acc[i][nt][c] = 0.f;

    issue(0, 0);
    asm volatile("cp.async.commit_group;" ::: "memory");
    issue(1, 1);
    asm volatile("cp.async.commit_group;" ::: "memory");

    int stg = 0;
    for (int ktb = 0; ktb < KT2; ++ktb) {
        asm volatile("cp.async.wait_group 1;" ::: "memory");
        __syncthreads();
        const uint32_t* st = smg + stg * 8192;
#pragma unroll
        for (int sk = 0; sk < 4; ++sk) {
            const uint32_t* ab = st + sk * 1024;
            const uint32_t* bb = st + 4096 + sk * 1024;
            uint4 a[2];
#pragma unroll
            for (int i = 0; i < 2; i++)
                a[i] = *(const uint4*)&ab[(mg*2 + i) * 128 + lane*4];
            uint2 bf[8];
#pragma unroll
            for (int nt = 0; nt < 8; nt++)
                bf[nt] = *(const uint2*)&bb[(ng*8 + nt) * 64 + lane*2];
#pragma unroll
            for (int i = 0; i < 2; i++)
#pragma unroll
                for (int nt = 0; nt < 8; nt++)
                    mma_tf32(acc[i][nt], a[i].x, a[i].y, a[i].z, a[i].w,
                             bf[nt].x, bf[nt].y);
        }
        if (ktb + 2 < KT2) {
            const int ns = (stg + 2 >= 3) ? stg - 1 : stg + 2;
            issue(ktb + 2, ns);
        }
        asm volatile("cp.async.commit_group;" ::: "memory");
        stg = (stg + 1 == 3) ? 0 : stg + 1;
    }

#pragma unroll
    for (int i = 0; i < 2; i++) {
        const int r0 = bm + (mg*2 + i) * 16 + qr;
#pragma unroll
        for (int nt = 0; nt < 8; nt++) {
            const int c0 = bn + (ng*8 + nt) * 8 + 2*qc;
            float v0 = acc[i][nt][0], v1 = acc[i][nt][1];
            float v2 = acc[i][nt][2], v3 = acc[i][nt][3];
            if (BIAS) {
                const float b0 = __ldg(bias + c0), b1 = __ldg(bias + c0 + 1);
                v0 += b0; v1 += b1; v2 += b0; v3 += b1;
            }
            *(float2*)(C + (size_t)r0       * N + c0) = make_float2(v0, v1);
            *(float2*)(C + (size_t)(r0 + 8) * N + c0) = make_float2(v2, v3);
        }
    }
}

// =====================================================================
// Feature kernel: half-chunk blocks, 2 CTAs/SM, proj frags from gmem.
// smem (u32): APK 8*516=4128 ; sm_e aliases base (64*264=16896)
//             RMAX @16896: 256 -> total 17152 u32 = 68608 B
// =====================================================================
#define FAPK_STRIDE 516
#define FRMAX_BASE  16896
#define FEAT_SMEM_BYTES (17152 * 4)

__global__ __launch_bounds__(256, 2)
void feature_mma(const uint32_t* __restrict__ Ppk)
{
    extern __shared__ uint32_t smu[];
    uint32_t* APK = smu;
    float*    sm_e = (float*)smu;
    float*    RMAX = (float*)(smu + FRMAX_BASE);

    const int cid  = blockIdx.x;
    const int isK  = blockIdx.y & 1;
    const int half = blockIdx.y >> 1;
    const int b  = cid >> 8;
    const int h  = (cid >> 5) & 7;
    const int cc = cid & 31;
    const size_t row0h  = (size_t)b * SEQ + (size_t)cc * CSZ + half * 64;
    const int   colbase = isK * DIMM + h * DHD;
    const float scale   = isK ? 1.0f : 0.125f;
    const int STR = isK ? 264 : 260;
    const int tid  = threadIdx.x;
    const int lane = tid & 31;
    const int warp = tid >> 5;
    const int wgm  = warp >> 2;
    const int fg   = warp & 3;
    const int qr   = lane >> 2;
    const int qc   = lane & 3;

#pragma unroll
    for (int it = 0; it < 4; ++it) {
        const int idx4 = it * 256 + tid;
        const int s  = idx4 >> 4;
        const int d4 = (idx4 & 15) * 4;
        float4 v = *(const float4*)(g_qkv + (row0h + s) * QKVN + colbase + d4);
        const int ks   = d4 >> 3;
        const int hi   = (d4 >> 2) & 1;
        const int sub  = s >> 4;
        const int qrS  = s & 7;
        const int halfS= (s >> 3) & 1;
        const int word = hi * 2 + halfS;
        uint32_t* base = APK + ks * FAPK_STRIDE + sub * 128 + (qrS << 4);
        base[0*4 + word] = f2tf32(v.x * scale);
        base[1*4 + word] = f2tf32(v.y * scale);
        base[2*4 + word] = f2tf32(v.z * scale);
        base[3*4 + word] = f2tf32(v.w * scale);
    }
    __syncthreads();

    float acc[2][8][4];
#pragma unroll
    for (int mt = 0; mt < 2; mt++)
#pragma unroll
        for (int nt = 0; nt < 8; nt++)
#pragma unroll
            for (int c = 0; c < 4; c++) acc[mt][nt][c] = 0.f;

    const int rl4 = lane * 4;
#pragma unroll
    for (int ks = 0; ks < 8; ++ks) {
        const uint32_t* abase = APK + ks * FAPK_STRIDE;
        const uint32_t* pbase = Ppk + ks * 2048;
        uint4 a0 = *(const uint4*)&abase[(wgm*2 + 0) * 128 + rl4];
        uint4 a1 = *(const uint4*)&abase[(wgm*2 + 1) * 128 + rl4];
#pragma unroll
        for (int nt = 0; nt < 8; nt++) {
            uint2 bb = __ldg((const uint2*)&pbase[(fg*8 + nt) * 64 + lane*2]);
            mma_tf32(acc[0][nt], a0.x, a0.y, a0.z, a0.w, bb.x, bb.y);
            mma_tf32(acc[1][nt], a1.x, a1.y, a1.z, a1.w, bb.x, bb.y);
        }
    }

    float mloc[2][2];
#pragma unroll
    for (int mt = 0; mt < 2; mt++)
#pragma unroll
        for (int hh = 0; hh < 2; hh++) {
            float m = -1e30f;
#pragma unroll
            for (int nt = 0; nt < 8; nt++) {
                m = fmaxf(m, acc[mt][nt][hh*2+0]);
                m = fmaxf(m, acc[mt][nt][hh*2+1]);
            }
            m = fmaxf(m, __shfl_xor_sync(0xffffffffu, m, 1));
            m = fmaxf(m, __shfl_xor_sync(0xffffffffu, m, 2));
            mloc[mt][hh] = m;
        }
    if (qc == 0) {
#pragma unroll
        for (int mt = 0; mt < 2; mt++)
#pragma unroll
            for (int hh = 0; hh < 2; hh++)
                RMAX[fg*64 + wgm*32 + mt*16 + hh*8 + qr] = mloc[mt][hh];
    }
    __syncthreads();

    float rm[2][2];
#pragma unroll
    for (int mt = 0; mt < 2; mt++)
#pragma unroll
        for (int hh = 0; hh < 2; hh++) {
            const int row = wgm*32 + mt*16 + hh*8 + qr;
            float m = fmaxf(RMAX[row], RMAX[64 + row]);
            m = fmaxf(m, RMAX[128 + row]);
            rm[mt][hh] = fmaxf(m, RMAX[192 + row]);
        }

#pragma unroll
    for (int mt = 0; mt < 2; mt++)
#pragma unroll
        for (int hh = 0; hh < 2; hh++) {
            const int row = wgm*32 + mt*16 + hh*8 + qr;
#pragma unroll
            for (int nt = 0; nt < 8; nt++) {
                const int f = fg*64 + nt*8 + 2*qc;
                float e0 = __expf(acc[mt][nt][hh*2+0] - rm[mt][hh]);
                float e1 = __expf(acc[mt][nt][hh*2+1] - rm[mt][hh]);
                sm_e[row*STR + f]     = __uint_as_float(f2tf32(e0));
                sm_e[row*STR + f + 1] = __uint_as_float(f2tf32(e1));
            }
        }
    __syncthreads();

    if (isK) {
        uint32_t* outp = (uint32_t*)g_kp + (size_t)cid * 32768;
#pragma unroll
        for (int it = 0; it < 16; ++it) {
            const int gid = it * 256 + tid;
            const int ln  = gid & 31;
            const int sub = (gid >> 5) & 15;
            const int ksl = gid >> 9;
            const int ks  = half*8 + ksl;
            const int qc2 = ln & 3, qr2 = ln >> 2;
            const int s0l = ksl*8 + qc2;
            const int f0  = sub*16 + qr2;
            uint4 u;
            u.x = __float_as_uint(sm_e[s0l*264 + f0]);
            u.y = __float_as_uint(sm_e[s0l*264 + f0 + 8]);
            u.z = __float_as_uint(sm_e[(s0l+4)*264 + f0]);
            u.w = __float_as_uint(sm_e[(s0l+4)*264 + f0 + 8]);
            *(uint4*)(outp + (size_t)(ks*2048 + sub*128 + ln*4)) = u;
        }
        float s = 0.f;
#pragma unroll 8
        for (int r = 0; r < 64; ++r) s += sm_e[r*264 + tid];
        g_ksumP[((size_t)half * NCHUNK + cid) * NF + tid] = s;
    } else {
        uint32_t* outp = (uint32_t*)g_qp + (size_t)cid * 32768;
#pragma unroll
        for (int it = 0; it < 16; ++it) {
            const int gid = it * 256 + tid;
            const int ln  = gid & 31;
            const int subl = (gid >> 5) & 3;
            const int ks  = gid >> 7;
            const int sub = half*4 + subl;
            const int qc2 = ln & 3, qr2 = ln >> 2;
            const int r0l = subl*16 + qr2;
            const int f0  = ks*8 + qc2;
            uint4 u;
            u.x = __float_as_uint(sm_e[r0l*260 + f0]);
            u.y = __float_as_uint(sm_e[(r0l+8)*260 + f0]);
            u.z = __float_as_uint(sm_e[r0l*260 + f0 + 4]);
            u.w = __float_as_uint(sm_e[(r0l+8)*260 + f0 + 4]);
            *(uint4*)(outp + (size_t)(ks*1024 + sub*128 + ln*4)) = u;
        }
    }
}

// =====================================================================
// Fused ctx + out kernel (P1 unroll 8, P2 unroll 8).
// smem (u32): region0 @0: 16384 | VBp @16384: 8192 | SKu @24576: 256
// =====================================================================
#define CO_SMEM_BYTES (24832 * 4)

__global__ __launch_bounds__(256, 2)
void ctx_out_mma()
{
    extern __shared__ uint32_t smu[];
    float*    vpl = (float*)smu;
    uint32_t* CBp = smu;
    uint32_t* ATs = smu;
    uint32_t* VBp = smu + 16384;
    uint32_t* SKu = smu + 24576;

    const int cid = blockIdx.x;
    const int b  = cid >> 8;
    const int h  = (cid >> 5) & 7;
    const int cc = cid & 31;
    const size_t row0 = (size_t)b * SEQ + (size_t)cc * CSZ;
    const int vcol = 2 * DIMM + h * DHD;
    const int tid  = threadIdx.x;
    const int lane = tid & 31;
    const int warp = tid >> 5;
    const int qr   = lane >> 2;
    const int qc   = lane & 3;

    const uint32_t* kbase = (const uint32_t*)g_kp + (size_t)cid * 32768;
    const uint32_t* qbase = (const uint32_t*)g_qp + (size_t)cid * 32768;

#pragma unroll
    for (int it = 0; it < 8; ++it) {
        const int idx4 = it * 256 + tid;
        const int s  = idx4 >> 4;
        const int d4 = (idx4 & 15) * 4;
        *(float4*)(vpl + s*72 + d4) =
            *(const float4*)(g_qkv + (row0 + s) * QKVN + vcol + d4);
    }
    if (tid < NF)
        SKu[tid] = f2tf32(g_ksumP[(size_t)cid * NF + tid] +
                          g_ksumP[((size_t)NCHUNK + cid) * NF + tid]);
    __syncthreads();

#pragma unroll
    for (int it = 0; it < 16; ++it) {
        const int wid2 = it * 256 + tid;
        const int ln   = wid2 & 31;
        const int nsub = (wid2 >> 5) & 7;
        const int ks   = wid2 >> 8;
        const int qc2 = ln & 3, qr2 = ln >> 2;
        const int s0 = ks*8 + qc2, d0 = nsub*8 + qr2;
        uint2 u;
        u.x = f2tf32(vpl[s0*72 + d0]);
        u.y = f2tf32(vpl[(s0+4)*72 + d0]);
        *(uint2*)(VBp + wid2*2) = u;
    }
    __syncthreads();

    float acc[2][8][4];
#pragma unroll
    for (int mt = 0; mt < 2; mt++)
#pragma unroll
        for (int nt = 0; nt < 8; nt++)
#pragma unroll
            for (int c = 0; c < 4; c++) acc[mt][nt][c] = 0.f;

#pragma unroll 8
    for (int ks = 0; ks < 16; ++ks) {
        uint4 a0 = *(const uint4*)(kbase + ks*2048 + (warp*2 + 0)*128 + lane*4);
        uint4 a1 = *(const uint4*)(kbase + ks*2048 + (warp*2 + 1)*128 + lane*4);
#pragma unroll
        for (int nt = 0; nt < 8; nt++) {
            uint2 bb = *(const uint2*)(VBp + ks*512 + nt*64 + lane*2);
            mma_tf32(acc[0][nt], a0.x, a0.y, a0.z, a0.w, bb.x, bb.y);
            mma_tf32(acc[1][nt], a1.x, a1.y, a1.z, a1.w, bb.x, bb.y);
        }
    }
    __syncthreads();

#pragma unroll
    for (int mt = 0; mt < 2; mt++)
#pragma unroll
        for (int nt = 0; nt < 8; nt++)
#pragma unroll
            for (int c = 0; c < 4; c++) {
                const int f = warp*32 + mt*16 + qr + ((c & 2) << 2);
                const int d = nt*8 + 2*qc + (c & 1);
                CBp[(f>>3)*512 + (d>>3)*64 + ((d&7)*4 + (f&3))*2 + ((f>>2)&1)]
                    = f2tf32(acc[mt][nt][c]);
            }
    __syncthreads();

    float acc2[8][4];
    float accD[4];
#pragma unroll
    for (int c = 0; c < 4; c++) accD[c] = 0.f;
#pragma unroll
    for (int nt = 0; nt < 8; nt++)
#pragma unroll
        for (int c = 0; c < 4; c++) acc2[nt][c] = 0.f;

#pragma unroll 8
    for (int ks = 0; ks < 32; ++ks) {
        uint4 a0 = *(const uint4*)(qbase + ks*1024 + warp*128 + lane*4);
        const uint32_t sb0 = SKu[ks*8 + qc];
        const uint32_t sb1 = SKu[ks*8 + qc + 4];
#pragma unroll
        for (int nt = 0; nt < 8; nt++) {
            uint2 bb = *(const uint2*)(CBp + ks*512 + nt*64 + lane*2);
            mma_tf32(acc2[nt], a0.x, a0.y, a0.z, a0.w, bb.x, bb.y);
        }
        mma_tf32(accD, a0.x, a0.y, a0.z, a0.w, sb0, sb1);
    }
    __syncthreads();

    {
        const float d0 = 1.0f / (accD[0] + 1e-4f);
        const float d1 = 1.0f / (accD[2] + 1e-4f);
#pragma unroll
        for (int nt = 0; nt < 8; nt++) {
#pragma unroll
            for (int c = 0; c < 4; c++) {
                const int r   = warp*16 + qr + (c & 2) * 4;
                const int col = nt*8 + 2*qc + (c & 1);
                const float dinv = (c & 2) ? d1 : d0;
                const int idx = (col>>4)*2048 + ((col>>3)&1)*1024 + (r>>4)*128
                              + ((r&7)*4 + (col&3))*4 + ((col>>2)&1)*2 + ((r>>3)&1);
                ATs[idx] = f2tf32(acc2[nt][c] * dinv);
            }
        }
    }
    __syncthreads();

    {
        const int tile = b*32 + cc;
        uint4* gdst = (uint4*)(g_att + (size_t)tile * 65536 + (size_t)h * 8192);
        const uint4* ssrc = (const uint4*)ATs;
#pragma unroll
        for (int i = 0; i < 8; ++i)
            gdst[i*256 + tid] = ssrc[i*256 + tid];
    }
}

// =====================================================================
// launch
// =====================================================================
extern "C" void kernel_launch(void* const* d_in, const int* in_sizes, int n_in,
                              void* d_out, int out_size)
{
    const float *x = nullptr, *wqkv = nullptr, *wout = nullptr,
                *bout = nullptr, *proj = nullptr;
    for (int i = 0; i < n_in; i++) {
        switch (in_sizes[i]) {
            case MTOK * DIMM:  x    = (const float*)d_in[i]; break;
            case QKVN * DIMM:  wqkv = (const float*)d_in[i]; break;
            case DIMM * DIMM:  wout = (const float*)d_in[i]; break;
            case DIMM:         bout = (const float*)d_in[i]; break;
            case NF * DHD:     proj = (const float*)d_in[i]; break;
        }
    }

    cudaFuncSetAttribute(feature_mma, cudaFuncAttributeMaxDynamicSharedMemorySize, FEAT_SMEM_BYTES);
    cudaFuncSetAttribute(ctx_out_mma, cudaFuncAttributeMaxDynamicSharedMemorySize, CO_SMEM_BYTES);
    cudaFuncSetAttribute(tgemm_nt<false>, cudaFuncAttributeMaxDynamicSharedMemorySize, TG_SMEM_BYTES);
    cudaFuncSetAttribute(tgemm_nt<true>,  cudaFuncAttributeMaxDynamicSharedMemorySize, TG_SMEM_BYTES);

    float *qkvp = nullptr;
    uint32_t *attp = nullptr, *xr = nullptr, *wqr = nullptr, *wor = nullptr, *ppk = nullptr;
    cudaGetSymbolAddress((void**)&qkvp, g_qkv);
    cudaGetSymbolAddress((void**)&attp, g_att);
    cudaGetSymbolAddress((void**)&xr,   g_xr);
    cudaGetSymbolAddress((void**)&wqr,  g_wqr);
    cudaGetSymbolAddress((void**)&wor,  g_wor);
    cudaGetSymbolAddress((void**)&ppk,  g_ppk);

    // 0) pack operands into tf32 fragment layouts
    pack_A_tf32<<<(MTOK*DIMM/4 + 255)/256, 256>>>(x, xr, MTOK*DIMM/4);
    pack_rest<<<(NB1 + NB2 + 8192 + 255)/256, 256>>>(wqkv, wout, proj, wqr, wor, ppk);

    // 1) qkv = x @ w_qkv^T
    tgemm_nt<false><<<dim3(QKVN/128, MTOK/128), 256, TG_SMEM_BYTES>>>(
        xr, wqr, nullptr, qkvp, MTOK, QKVN, DIMM);
    // 2) q'/k' feature maps + ksum partials
    feature_mma<<<dim3(NCHUNK, 4), 256, FEAT_SMEM_BYTES>>>(ppk);
    // 3+4) fused ctx + out -> packed att
    ctx_out_mma<<<NCHUNK, 256, CO_SMEM_BYTES>>>();
    // 5) final = att @ w_out^T + b_out
    tgemm_nt<true><<<dim3(DIMM/128, MTOK/128), 256, TG_SMEM_BYTES>>>(
        attp, wor, bout, (float*)d_out, MTOK, DIMM, DIMM);
}